// round 5
// baseline (speedup 1.0000x reference)
#include <cuda_runtime.h>

#define B_ 64
#define R_ 32
#define N_ 16384
#define D_ 64
#define O_ 8
#define THREADS_ 512
#define NPT_ (N_ / THREADS_)   /* 32 n per thread */

// ---------------------------------------------------------------------------
// Single fused kernel. grid = B (one block per batch), block = 512.
// Phase 0: inline mask-dtype probe (first 2KB of each mask array).
// Phase 1: scan all N masks for this b; gather+normalize+accumulate the
//          ~0.74% valid context rows into shared s_acc[64].
// Phase 2: 16 warps finalize r = warp, warp+16 directly from smem.
// ---------------------------------------------------------------------------
__global__ __launch_bounds__(THREADS_)
void ssfw_fused(const float* __restrict__ l_local,
                const float* __restrict__ hctx,
                const float* __restrict__ lambda_so,
                const int*   __restrict__ center_o,
                const int*   __restrict__ o_types,
                const void*  __restrict__ adj,
                const void*  __restrict__ two,
                float*       __restrict__ out) {
    const int b   = blockIdx.x;
    const int tid = threadIdx.x;

    // NOTE: s_acc MUST be 16B-aligned — Phase 2 reads it through float2*.
    __shared__ __align__(16) float s_acc[D_];
    __shared__ int sh_flags;
    __shared__ int s_cnt;
    if (tid == 0) { sh_flags = 0; s_cnt = 0; }
    if (tid < D_) s_acc[tid] = 0.0f;
    __syncthreads();

    // ---- Phase 0: probe mask dtype from raw bits (deterministic, L2-hot) ----
    {
        unsigned va = ((const unsigned*)adj)[tid];
        unsigned vt = ((const unsigned*)two)[tid];
        int fl = 0;
        #pragma unroll
        for (int j = 0; j < 2; j++) {
            unsigned v = j ? vt : va;
            if (v == 0x3F800000u)        fl |= 2;   // 1.0f pattern -> float32 masks
            else if (v != 0u && v != 1u) fl |= 1;   // packed bytes -> uint8 masks
        }
        if (fl) atomicOr(&sh_flags, fl);
    }
    __syncthreads();
    const int flags = sh_flags;
    const int kind  = (flags & 1) ? 0 : ((flags & 2) ? 2 : 1);  // 0=u8, 1=i32, 2=f32

    // ---- Phase 1: mask scan + sparse gather ----
    const int       ctr  = center_o[b];
    const long long base = (long long)b * N_ + tid * NPT_;   // 32 consecutive n
    int localc = 0;

    #pragma unroll
    for (int g = 0; g < NPT_ / 4; g++) {        // 8 groups of 4 n
        const long long mi = base + g * 4;
        unsigned m[4];
        if (kind == 1) {
            uint4 va = *(const uint4*)((const int*)adj + mi);
            uint4 vt = *(const uint4*)((const int*)two + mi);
            m[0] = va.x | vt.x; m[1] = va.y | vt.y;
            m[2] = va.z | vt.z; m[3] = va.w | vt.w;
        } else if (kind == 0) {
            unsigned va = *(const unsigned*)((const unsigned char*)adj + mi);
            unsigned vt = *(const unsigned*)((const unsigned char*)two + mi);
            unsigned u  = va | vt;
            m[0] = u & 0xffu;         m[1] = (u >> 8) & 0xffu;
            m[2] = (u >> 16) & 0xffu; m[3] = u >> 24;
        } else {
            float4 va = *(const float4*)((const float*)adj + mi);
            float4 vt = *(const float4*)((const float*)two + mi);
            m[0] = (va.x != 0.0f) || (vt.x != 0.0f);
            m[1] = (va.y != 0.0f) || (vt.y != 0.0f);
            m[2] = (va.z != 0.0f) || (vt.z != 0.0f);
            m[3] = (va.w != 0.0f) || (vt.w != 0.0f);
        }

        if (m[0] | m[1] | m[2] | m[3]) {
            const int4 ov = *(const int4*)(o_types + mi);
            const int  oo[4] = { ov.x, ov.y, ov.z, ov.w };
            #pragma unroll
            for (int j = 0; j < 4; j++) {
                if (m[j] && oo[j] == ctr) {
                    localc++;
                    const float4* row = (const float4*)(hctx + (mi + j) * D_);
                    float4 v[16];
                    float sq = 0.0f;
                    #pragma unroll
                    for (int i = 0; i < 16; i++) {
                        v[i] = row[i];
                        sq += v[i].x * v[i].x + v[i].y * v[i].y
                            + v[i].z * v[i].z + v[i].w * v[i].w;
                    }
                    float rn = rsqrtf(fmaxf(sq, 1e-12f));
                    #pragma unroll
                    for (int i = 0; i < 16; i++) {
                        atomicAdd(&s_acc[4 * i + 0], v[i].x * rn);
                        atomicAdd(&s_acc[4 * i + 1], v[i].y * rn);
                        atomicAdd(&s_acc[4 * i + 2], v[i].z * rn);
                        atomicAdd(&s_acc[4 * i + 3], v[i].w * rn);
                    }
                }
            }
        }
    }
    if (localc) atomicAdd(&s_cnt, localc);
    __syncthreads();

    // ---- Phase 2: finalize. 16 warps; warp w handles r = w and w+16. ----
    const int warp = tid >> 5;
    const int lane = tid & 31;
    const float nv = (float)s_cnt;
    const float2 sv = *(const float2*)(&s_acc[lane * 2]);   // 8B-aligned now

    #pragma unroll
    for (int rr = 0; rr < 2; rr++) {
        const int r = warp + rr * 16;
        const float2* lrow = (const float2*)(l_local + ((long long)b * R_ + r) * D_);
        float2 lv = lrow[lane];

        float sq = lv.x * lv.x + lv.y * lv.y;
        float dp = lv.x * sv.x + lv.y * sv.y;
        #pragma unroll
        for (int o = 16; o > 0; o >>= 1) {
            sq += __shfl_xor_sync(0xffffffffu, sq, o);
            dp += __shfl_xor_sync(0xffffffffu, dp, o);
        }
        if (lane == 0) {
            float rinv = rsqrtf(fmaxf(sq, 1e-12f));
            float avg  = rinv * dp / fmaxf(nv, 1e-9f);
            float lam  = lambda_so[r * O_ + ctr];
            float w    = fmaxf(lam / fmaxf(nv, 1.0f), 0.0f) * (1.0f - avg);
            out[b * R_ + r] = w;
        }
    }
}

// ---------------------------------------------------------------------------
// Launch contract
// Inputs (metadata order): 0 l_local [B,R,D] f32, 1 h_context [B,N,D] f32,
// 2 lambda_so [R,O] f32, 3 center_o [B] i32, 4 o_types [B,N] i32,
// 5 adj_mask [B,N] bool, 6 two_hop_mask [B,N] bool.  Output [B,R] f32.
// ---------------------------------------------------------------------------
extern "C" void kernel_launch(void* const* d_in, const int* in_sizes, int n_in,
                              void* d_out, int out_size) {
    const float* l_local   = (const float*)d_in[0];
    const float* h_context = (const float*)d_in[1];
    const float* lambda_so = (const float*)d_in[2];
    const int*   center_o  = (const int*)d_in[3];
    const int*   o_types   = (const int*)d_in[4];
    const void*  adj_mask  = d_in[5];
    const void*  two_mask  = d_in[6];
    float*       out       = (float*)d_out;

    ssfw_fused<<<B_, THREADS_>>>(l_local, h_context, lambda_so, center_o,
                                 o_types, adj_mask, two_mask, out);
}

// round 6
// speedup vs baseline: 3.0450x; 3.0450x over previous
#include <cuda_runtime.h>

#define B_ 64
#define R_ 32
#define N_ 16384
#define D_ 64
#define O_ 8
#define SPLIT_ 16
#define CHUNK_ (N_ / SPLIT_)    /* 1024 = 256 threads * 4 n */
#define THREADS_ 256

// Plain-store partials: every slot written every launch -> no zeroing pass.
__device__ __align__(16) float g_part[B_][SPLIT_][D_];
__device__ float g_cnt[B_][SPLIT_];
// Completion counters (zero-init .bss; finalizer resets them each launch).
__device__ unsigned g_done[B_];

// ---------------------------------------------------------------------------
// Single launch. grid = (B, SPLIT), block = 256; thread owns 4 consecutive n
// (warp = 512 contiguous mask bytes -> fully coalesced).
// The last block to finish each b finalizes that b's 32 outputs.
// ---------------------------------------------------------------------------
__global__ __launch_bounds__(THREADS_)
void ssfw_fused(const float* __restrict__ l_local,
                const float* __restrict__ hctx,
                const float* __restrict__ lambda_so,
                const int*   __restrict__ center_o,
                const int*   __restrict__ o_types,
                const void*  __restrict__ adj,
                const void*  __restrict__ two,
                float*       __restrict__ out) {
    const int b    = blockIdx.x;
    const int part = blockIdx.y;
    const int tid  = threadIdx.x;

    __shared__ __align__(16) float s_acc[D_];
    __shared__ int  sh_bytes;       // 1 if masks are packed bytes
    __shared__ int  s_cnt;
    __shared__ int  s_last;
    if (tid == 0) { sh_bytes = 0; s_cnt = 0; }
    if (tid < D_) s_acc[tid] = 0.0f;

    // ---- issue all round-1 loads up front (independent; MLP) ----
    // probe: first 512 u32 of each mask array (identical across blocks, L2-hot)
    unsigned pa0 = ((const unsigned*)adj)[tid];
    unsigned pt0 = ((const unsigned*)two)[tid];
    unsigned pa1 = ((const unsigned*)adj)[tid + 256];
    unsigned pt1 = ((const unsigned*)two)[tid + 256];

    const int       n_base = part * CHUNK_ + tid * 4;
    const long long mi     = (long long)b * N_ + n_base;

    // speculative byte-view mask loads (valid for any dtype >= 1 byte/elem)
    unsigned bva = *(const unsigned*)((const unsigned char*)adj + mi);
    unsigned bvt = *(const unsigned*)((const unsigned char*)two + mi);
    // o_types: needed on every path
    const int4 ov = *(const int4*)(o_types + mi);
    const int  ctr = center_o[b];

    // classify: any probe word outside {0, 1, 0x3F800000} => packed bytes
    {
        int isb = 0;
        #pragma unroll
        for (int j = 0; j < 4; j++) {
            unsigned v = (j == 0) ? pa0 : (j == 1) ? pt0 : (j == 2) ? pa1 : pt1;
            if (v != 0u && v != 1u && v != 0x3F800000u) isb = 1;
        }
        if (isb) atomicOr(&sh_bytes, 1);
    }
    __syncthreads();

    unsigned m[4];
    if (sh_bytes) {
        unsigned u = bva | bvt;
        m[0] = u & 0xffu;         m[1] = (u >> 8) & 0xffu;
        m[2] = (u >> 16) & 0xffu; m[3] = u >> 24;
    } else {
        // word masks: nonzero bits == true for BOTH int32 0/1 and f32 0.0/1.0
        uint4 va = *(const uint4*)((const int*)adj + mi);
        uint4 vt = *(const uint4*)((const int*)two + mi);
        m[0] = va.x | vt.x; m[1] = va.y | vt.y;
        m[2] = va.z | vt.z; m[3] = va.w | vt.w;
    }

    int localc = 0;
    if (m[0] | m[1] | m[2] | m[3]) {
        const int oo[4] = { ov.x, ov.y, ov.z, ov.w };
        #pragma unroll
        for (int j = 0; j < 4; j++) {
            if (m[j] && oo[j] == ctr) {
                localc++;
                const float4* row = (const float4*)(hctx + (mi + j) * D_);
                float4 v[16];
                float sq = 0.0f;
                #pragma unroll
                for (int i = 0; i < 16; i++) {
                    v[i] = row[i];
                    sq += v[i].x * v[i].x + v[i].y * v[i].y
                        + v[i].z * v[i].z + v[i].w * v[i].w;
                }
                float rn = rsqrtf(fmaxf(sq, 1e-12f));
                #pragma unroll
                for (int i = 0; i < 16; i++) {
                    atomicAdd(&s_acc[4 * i + 0], v[i].x * rn);
                    atomicAdd(&s_acc[4 * i + 1], v[i].y * rn);
                    atomicAdd(&s_acc[4 * i + 2], v[i].z * rn);
                    atomicAdd(&s_acc[4 * i + 3], v[i].w * rn);
                }
            }
        }
    }
    if (localc) atomicAdd(&s_cnt, localc);
    __syncthreads();

    // ---- publish partials ----
    if (tid < D_) g_part[b][part][tid] = s_acc[tid];
    if (tid == 0) g_cnt[b][part] = (float)s_cnt;

    // ---- last-block-done detection ----
    if (tid == 0) {
        __threadfence();
        unsigned old = atomicAdd(&g_done[b], 1u);
        s_last = (old == SPLIT_ - 1);
    }
    __syncthreads();
    if (!s_last) return;

    // ---- finalize b (this block only) ----
    __shared__ __align__(16) float s_sum[D_];
    __shared__ float s_nv;
    if (tid < D_) {
        float acc = 0.0f;
        #pragma unroll
        for (int p = 0; p < SPLIT_; p++) acc += g_part[b][p][tid];
        s_sum[tid] = acc;
    }
    if (tid == 0) {
        float nv = 0.0f;
        #pragma unroll
        for (int p = 0; p < SPLIT_; p++) nv += g_cnt[b][p];
        s_nv = nv;
        g_done[b] = 0;                  // reset for next graph replay
    }
    __syncthreads();

    const int warp = tid >> 5;          // 8 warps
    const int lane = tid & 31;
    const float  nv = s_nv;
    const float2 sv = *(const float2*)(&s_sum[lane * 2]);

    #pragma unroll
    for (int rr = 0; rr < 4; rr++) {    // warp w handles r = w, w+8, w+16, w+24
        const int r = warp + rr * 8;
        const float2* lrow = (const float2*)(l_local + ((long long)b * R_ + r) * D_);
        float2 lv = lrow[lane];

        float sq = lv.x * lv.x + lv.y * lv.y;
        float dp = lv.x * sv.x + lv.y * sv.y;
        #pragma unroll
        for (int o = 16; o > 0; o >>= 1) {
            sq += __shfl_xor_sync(0xffffffffu, sq, o);
            dp += __shfl_xor_sync(0xffffffffu, dp, o);
        }
        if (lane == 0) {
            float rinv = rsqrtf(fmaxf(sq, 1e-12f));
            float avg  = rinv * dp / fmaxf(nv, 1e-9f);
            float lam  = lambda_so[r * O_ + ctr];
            float w    = fmaxf(lam / fmaxf(nv, 1.0f), 0.0f) * (1.0f - avg);
            out[b * R_ + r] = w;
        }
    }
}

// ---------------------------------------------------------------------------
// Launch contract
// Inputs (metadata order): 0 l_local [B,R,D] f32, 1 h_context [B,N,D] f32,
// 2 lambda_so [R,O] f32, 3 center_o [B] i32, 4 o_types [B,N] i32,
// 5 adj_mask [B,N] bool, 6 two_hop_mask [B,N] bool.  Output [B,R] f32.
// ---------------------------------------------------------------------------
extern "C" void kernel_launch(void* const* d_in, const int* in_sizes, int n_in,
                              void* d_out, int out_size) {
    const float* l_local   = (const float*)d_in[0];
    const float* h_context = (const float*)d_in[1];
    const float* lambda_so = (const float*)d_in[2];
    const int*   center_o  = (const int*)d_in[3];
    const int*   o_types   = (const int*)d_in[4];
    const void*  adj_mask  = d_in[5];
    const void*  two_mask  = d_in[6];
    float*       out       = (float*)d_out;

    ssfw_fused<<<dim3(B_, SPLIT_), THREADS_>>>(l_local, h_context, lambda_so,
                                               center_o, o_types,
                                               adj_mask, two_mask, out);
}